// round 15
// baseline (speedup 1.0000x reference)
#include <cuda_runtime.h>
#include <cuda_bf16.h>

// B=1, H=16, S=4096, D=64, fp32, NO softmax.
// (Q K^T) V == Q (K^T V);  K^T V is [64x64] per head -> 64x fewer FLOPs.
// R15: bf16x3 (m16n8k16) compensated GEMMs.
//  ktv: 512 threads/block (2x warps/SM), ping-pong smem stages (1 sync/phase),
//       register-prefetch of next stage -> latency-bound fix.
#define HEADS 16
#define SEQ   4096
#define DIM   64
#define NSPLIT 32
#define CHUNK (SEQ / NSPLIT)   // 128 rows per partial block

__device__ __align__(16) float g_partial[HEADS * NSPLIT * DIM * DIM];  // 8 MB
__device__ __align__(16) float g_M[HEADS * DIM * DIM];                 // 256 KB

// ---- bf16 split/pack helpers ----------------------------------------------
__device__ __forceinline__ void split_bf16(float x, float& hi_f, __nv_bfloat16& hi,
                                           __nv_bfloat16& lo) {
    hi = __float2bfloat16_rn(x);
    hi_f = __bfloat162float(hi);
    lo = __float2bfloat16_rn(x - hi_f);
}
__device__ __forceinline__ void pack2(float x0, float x1, unsigned& whi, unsigned& wlo) {
    float h0f, h1f;
    __nv_bfloat16 h0, l0, h1, l1;
    split_bf16(x0, h0f, h0, l0);
    split_bf16(x1, h1f, h1, l1);
    __nv_bfloat162 ph = __halves2bfloat162(h0, h1);
    __nv_bfloat162 pl = __halves2bfloat162(l0, l1);
    whi = *(unsigned*)&ph;
    wlo = *(unsigned*)&pl;
}
__device__ __forceinline__ void mma_bf16(float* d, const unsigned* a, const unsigned* b) {
    asm("mma.sync.aligned.m16n8k16.row.col.f32.bf16.bf16.f32 "
        "{%0,%1,%2,%3}, {%4,%5,%6,%7}, {%8,%9}, {%0,%1,%2,%3};"
        : "+f"(d[0]), "+f"(d[1]), "+f"(d[2]), "+f"(d[3])
        : "r"(a[0]), "r"(a[1]), "r"(a[2]), "r"(a[3]), "r"(b[0]), "r"(b[1]));
}
__device__ __forceinline__ void mma_x3(float* acc, const unsigned* ah, const unsigned* al,
                                       const unsigned* bh, const unsigned* bl) {
    mma_bf16(acc, ah, bh);
    mma_bf16(acc, ah, bl);
    mma_bf16(acc, al, bh);
}

#define KSTR 72   // u32 row stride: ==8 mod 32 -> (8sp+g) gathers conflict-free

// ---------------------------------------------------------------------------
// Kernel 1: partial M = K_chunk^T @ V_chunk.  grid = HEADS*NSPLIT, 512 thr.
// Planes [sp=s/2][d]: word = bf16(s=2sp) | bf16(s=2sp+1)<<16  (mma k-pair).
// 16 warps: (wid&3) -> d1 block of 16; (wid>>2) -> d2 block of 16 (nt=2).
// Two 64-row ping-pong stages; register prefetch; ONE sync per phase.
// Dynamic smem: 2 stages * 4 planes * 32*KSTR u32 = 72 KB.
// ---------------------------------------------------------------------------
#define KTV_THREADS 512
#define ROWS_PER_STAGE 64           // 32 s-pairs
#define PLANE_WORDS (32 * KSTR)
#define STAGE_WORDS (4 * PLANE_WORDS)
#define KTV_SMEM (2 * STAGE_WORDS * 4)

__global__ __launch_bounds__(KTV_THREADS) void ktv_partial(const float* __restrict__ Kp,
                                                           const float* __restrict__ Vp) {
    extern __shared__ __align__(16) unsigned sm[];   // [2][4][32][KSTR]

    const int h   = blockIdx.x / NSPLIT;
    const int spl = blockIdx.x % NSPLIT;
    const float* Kh = Kp + ((size_t)h * SEQ + (size_t)spl * CHUNK) * DIM;
    const float* Vh = Vp + ((size_t)h * SEQ + (size_t)spl * CHUNK) * DIM;

    const int tid  = threadIdx.x;
    const int wid  = tid >> 5;
    const int lane = tid & 31;
    const int g = lane >> 2;      // 0..7
    const int t = lane & 3;       // 0..3
    const int d1_0 = (wid & 3) * 16;
    const int d2_0 = (wid >> 2) * 16;

    // staging slot: s-pair sp (0..31), col quad c4
    const int sp = tid >> 4;
    const int c4 = (tid & 15) << 2;

    float4 k0, k1, v0, v1;
    float acc[2][4] = {};

    auto fetch = [&](int t0) {
        k0 = *(const float4*)&Kh[(size_t)(t0 + 2 * sp) * DIM + c4];
        k1 = *(const float4*)&Kh[(size_t)(t0 + 2 * sp + 1) * DIM + c4];
        v0 = *(const float4*)&Vh[(size_t)(t0 + 2 * sp) * DIM + c4];
        v1 = *(const float4*)&Vh[(size_t)(t0 + 2 * sp + 1) * DIM + c4];
    };
    auto stash = [&](int st) {
        unsigned* Khi = sm + st * STAGE_WORDS;
        unsigned* Klo = Khi + PLANE_WORDS;
        unsigned* Vhi = Klo + PLANE_WORDS;
        unsigned* Vlo = Vhi + PLANE_WORDS;
        uint4 whi, wlo;
        pack2(k0.x, k1.x, whi.x, wlo.x);
        pack2(k0.y, k1.y, whi.y, wlo.y);
        pack2(k0.z, k1.z, whi.z, wlo.z);
        pack2(k0.w, k1.w, whi.w, wlo.w);
        *(uint4*)&Khi[sp * KSTR + c4] = whi;
        *(uint4*)&Klo[sp * KSTR + c4] = wlo;
        pack2(v0.x, v1.x, whi.x, wlo.x);
        pack2(v0.y, v1.y, whi.y, wlo.y);
        pack2(v0.z, v1.z, whi.z, wlo.z);
        pack2(v0.w, v1.w, whi.w, wlo.w);
        *(uint4*)&Vhi[sp * KSTR + c4] = whi;
        *(uint4*)&Vlo[sp * KSTR + c4] = wlo;
    };

    fetch(0);
    stash(0);
    __syncthreads();

    #pragma unroll
    for (int ph = 0; ph < CHUNK / ROWS_PER_STAGE; ph++) {
        if (ph < CHUNK / ROWS_PER_STAGE - 1)
            fetch((ph + 1) * ROWS_PER_STAGE);            // overlap LDG with MMA

        const unsigned* Khi = sm + (ph & 1) * STAGE_WORDS;
        const unsigned* Klo = Khi + PLANE_WORDS;
        const unsigned* Vhi = Klo + PLANE_WORDS;
        const unsigned* Vlo = Vhi + PLANE_WORDS;

        #pragma unroll
        for (int ks = 0; ks < 4; ks++) {                 // four k16 slabs (32 sp rows)
            const int sb = ks * 8;
            unsigned ah[4], al[4];
            ah[0] = Khi[(sb + t) * KSTR + d1_0 + g];
            al[0] = Klo[(sb + t) * KSTR + d1_0 + g];
            ah[1] = Khi[(sb + t) * KSTR + d1_0 + g + 8];
            al[1] = Klo[(sb + t) * KSTR + d1_0 + g + 8];
            ah[2] = Khi[(sb + t + 4) * KSTR + d1_0 + g];
            al[2] = Klo[(sb + t + 4) * KSTR + d1_0 + g];
            ah[3] = Khi[(sb + t + 4) * KSTR + d1_0 + g + 8];
            al[3] = Klo[(sb + t + 4) * KSTR + d1_0 + g + 8];
            #pragma unroll
            for (int nt = 0; nt < 2; nt++) {
                const int col = d2_0 + nt * 8 + g;
                unsigned bh[2], bl[2];
                bh[0] = Vhi[(sb + t) * KSTR + col];
                bl[0] = Vlo[(sb + t) * KSTR + col];
                bh[1] = Vhi[(sb + t + 4) * KSTR + col];
                bl[1] = Vlo[(sb + t + 4) * KSTR + col];
                mma_x3(acc[nt], ah, al, bh, bl);
            }
        }

        if (ph < CHUNK / ROWS_PER_STAGE - 1) {
            stash(ph ^ 1);        // other buffer: no pre-sync needed
            __syncthreads();      // visible before next phase's MMA
        }
    }

    float* outp = g_partial + ((size_t)h * NSPLIT + spl) * DIM * DIM;
    #pragma unroll
    for (int nt = 0; nt < 2; nt++) {
        const int col = d2_0 + nt * 8 + 2 * t;
        const int row = d1_0 + g;
        *(float2*)&outp[row * DIM + col]       = make_float2(acc[nt][0], acc[nt][1]);
        *(float2*)&outp[(row + 8) * DIM + col] = make_float2(acc[nt][2], acc[nt][3]);
    }
}

// ---------------------------------------------------------------------------
// Kernel 2: reduce NSPLIT partials -> g_M (fp32; qm packs at staging).
// ---------------------------------------------------------------------------
__global__ __launch_bounds__(256) void reduce_m() {
    const int idx = blockIdx.x * 256 + threadIdx.x;   // float4 index
    if (idx >= HEADS * DIM * DIM / 4) return;
    const int h = idx / (DIM * DIM / 4);
    const int e = idx % (DIM * DIM / 4);
    float4 s = make_float4(0.f, 0.f, 0.f, 0.f);
    #pragma unroll
    for (int p = 0; p < NSPLIT; p++) {
        const float4 tv = *(const float4*)&g_partial[(((size_t)h * NSPLIT + p) * DIM * DIM) + e * 4];
        s.x += tv.x; s.y += tv.y; s.z += tv.z; s.w += tv.w;
    }
    *(float4*)&g_M[(size_t)idx * 4] = s;
}

// ---------------------------------------------------------------------------
// Kernel 3: out = Q @ M.  Block = 64 q-rows x 64 cols, 256 thr (8 warps).
// Qhi/Qlo[q][dp] stride 36 (banks 4g+t distinct); Mhi/Mlo[dp][n] stride 72.
// Warps 4x2: (wid&3) -> 16-row group; (wid>>2) -> 32-col group (nt=4).
// ---------------------------------------------------------------------------
#define QSTR 36
#define QROWS 64
__global__ __launch_bounds__(256) void qm_gemm(const float* __restrict__ Qp,
                                               float* __restrict__ Op) {
    const int h  = blockIdx.x >> 6;            // 64 blocks per head
    const int r0 = (blockIdx.x & 63) * QROWS;

    __shared__ __align__(16) unsigned Qhi[QROWS][QSTR], Qlo[QROWS][QSTR];  // 18.4 KB
    __shared__ __align__(16) unsigned Mhi[32][KSTR],    Mlo[32][KSTR];     // 18.4 KB

    const int tid  = threadIdx.x;
    const int wid  = tid >> 5;
    const int lane = tid & 31;
    const int g = lane >> 2;
    const int t = lane & 3;
    const int rw = (wid & 3) * 16;     // q-row group of 16
    const int c0 = (wid >> 2) * 32;    // out col group of 32

    const float* Qh = Qp + ((size_t)h * SEQ + r0) * DIM;
    const float* Mh = g_M + (size_t)h * DIM * DIM;

    // stage Q: 64 rows x 32 dp words
    #pragma unroll
    for (int s = tid; s < QROWS * 8; s += 256) {
        const int r   = s >> 3;
        const int dp4 = (s & 7) << 2;
        const float4 qa = *(const float4*)&Qh[(size_t)r * DIM + 2 * dp4];
        const float4 qb = *(const float4*)&Qh[(size_t)r * DIM + 2 * dp4 + 4];
        uint4 whi, wlo;
        pack2(qa.x, qa.y, whi.x, wlo.x);
        pack2(qa.z, qa.w, whi.y, wlo.y);
        pack2(qb.x, qb.y, whi.z, wlo.z);
        pack2(qb.z, qb.w, whi.w, wlo.w);
        *(uint4*)&Qhi[r][dp4] = whi;
        *(uint4*)&Qlo[r][dp4] = wlo;
    }
    // stage M: 32 dp rows x 64 cols
    #pragma unroll
    for (int s = tid; s < 32 * 16; s += 256) {
        const int dp = s >> 4;
        const int c4 = (s & 15) << 2;
        const float4 m0 = *(const float4*)&Mh[(2 * dp) * DIM + c4];
        const float4 m1 = *(const float4*)&Mh[(2 * dp + 1) * DIM + c4];
        uint4 whi, wlo;
        pack2(m0.x, m1.x, whi.x, wlo.x);
        pack2(m0.y, m1.y, whi.y, wlo.y);
        pack2(m0.z, m1.z, whi.z, wlo.z);
        pack2(m0.w, m1.w, whi.w, wlo.w);
        *(uint4*)&Mhi[dp][c4] = whi;
        *(uint4*)&Mlo[dp][c4] = wlo;
    }
    __syncthreads();

    float acc[4][4] = {};

    #pragma unroll
    for (int ks = 0; ks < 4; ks++) {            // four k16 slabs (d = 64)
        const int db = ks * 8;
        unsigned ah[4], al[4];
        ah[0] = Qhi[rw + g][db + t];         al[0] = Qlo[rw + g][db + t];
        ah[1] = Qhi[rw + g + 8][db + t];     al[1] = Qlo[rw + g + 8][db + t];
        ah[2] = Qhi[rw + g][db + t + 4];     al[2] = Qlo[rw + g][db + t + 4];
        ah[3] = Qhi[rw + g + 8][db + t + 4]; al[3] = Qlo[rw + g + 8][db + t + 4];
        #pragma unroll
        for (int nt = 0; nt < 4; nt++) {
            const int col = c0 + nt * 8 + g;
            unsigned bh[2], bl[2];
            bh[0] = Mhi[db + t][col];     bl[0] = Mlo[db + t][col];
            bh[1] = Mhi[db + t + 4][col]; bl[1] = Mlo[db + t + 4][col];
            mma_x3(acc[nt], ah, al, bh, bl);
        }
    }

    float* Oh = Op + ((size_t)h * SEQ + r0) * DIM;
    #pragma unroll
    for (int nt = 0; nt < 4; nt++) {
        const int col = c0 + nt * 8 + 2 * t;
        const int row = rw + g;
        *(float2*)&Oh[(size_t)row * DIM + col]       = make_float2(acc[nt][0], acc[nt][1]);
        *(float2*)&Oh[(size_t)(row + 8) * DIM + col] = make_float2(acc[nt][2], acc[nt][3]);
    }
}

// ---------------------------------------------------------------------------
extern "C" void kernel_launch(void* const* d_in, const int* in_sizes, int n_in,
                              void* d_out, int out_size) {
    const float* q = (const float*)d_in[0];
    const float* k = (const float*)d_in[1];
    const float* v = (const float*)d_in[2];
    float* out = (float*)d_out;

    static int attr_done = 0;   // idempotent attribute set (not a work guard)
    if (!attr_done) {
        cudaFuncSetAttribute(ktv_partial, cudaFuncAttributeMaxDynamicSharedMemorySize, KTV_SMEM);
        attr_done = 1;
    }

    ktv_partial<<<HEADS * NSPLIT, KTV_THREADS, KTV_SMEM>>>(k, v);
    reduce_m<<<(HEADS * DIM * DIM / 4 + 255) / 256, 256>>>();
    qm_gemm<<<HEADS * (SEQ / QROWS), 256>>>(q, out);
}